// round 9
// baseline (speedup 1.0000x reference)
#include <cuda_runtime.h>
#include <cuda_fp16.h>
#include <math.h>
#include <stdint.h>

#define NN 100000
#define EE 1600000
#define DD 128
#define KP 68          // padded smem row stride in 32-bit words
#define FULLM 0xFFFFFFFFu

// ---------------- device scratch (no allocations allowed) ----------------
__device__ int    g_rowptr[NN + 1];
__device__ int    g_cnt[NN];          // zero-init; re-zeroed by k_scanC
__device__ int    g_cursor[NN];
__device__ float  g_dinv[NN];
__device__ int2   g_cedge[EE];        // (src, dinv[src] bits), grouped by dst
__device__ int    g_bsums[128];
__device__ __half g_x16[(size_t)NN * DD];  // fp16 copy of input x
__device__ __half g_f16[(size_t)NN * DD];  // layer-1 activations f

// ---------------- x -> fp16 ----------------
__global__ void k_cvt(const float* __restrict__ x, int total8) {
    int i = blockIdx.x * blockDim.x + threadIdx.x;
    if (i >= total8) return;
    const float4* x4 = (const float4*)x;
    float4 a = x4[i * 2], b = x4[i * 2 + 1];
    __half2 h0 = __floats2half2_rn(a.x, a.y);
    __half2 h1 = __floats2half2_rn(a.z, a.w);
    __half2 h2 = __floats2half2_rn(b.x, b.y);
    __half2 h3 = __floats2half2_rn(b.z, b.w);
    uint4 u;
    u.x = *(unsigned*)&h0; u.y = *(unsigned*)&h1;
    u.z = *(unsigned*)&h2; u.w = *(unsigned*)&h3;
    ((uint4*)g_x16)[i] = u;
}

// ---------------- edge dtype detection (per warp) ----------------
__device__ __forceinline__ int detect64(const int* __restrict__ eb) {
    unsigned nz = 0;
#pragma unroll
    for (int i = (threadIdx.x & 31); i < 128; i += 32)
        nz |= (eb[2 * i + 1] != 0);
    return __ballot_sync(FULLM, nz) == 0;
}

// ---------------- preprocessing (R7 formulation — fastest measured) ------
__global__ void k_hist(const int* __restrict__ eb, int e) {
    int is64 = detect64(eb);
    int i = blockIdx.x * blockDim.x + threadIdx.x;
    if (i >= e) return;
    int d = is64 ? eb[2 * (e + i)] : eb[e + i];
    atomicAdd(&g_cnt[d], 1);
}

__global__ void k_scanA(int n) {
    __shared__ int sh[1024];
    int gi = blockIdx.x * 1024 + threadIdx.x;
    int v = (gi < n) ? g_cnt[gi] : 0;
    sh[threadIdx.x] = v;
    __syncthreads();
    for (int off = 1; off < 1024; off <<= 1) {
        int x = sh[threadIdx.x];
        int y = (threadIdx.x >= off) ? sh[threadIdx.x - off] : 0;
        __syncthreads();
        sh[threadIdx.x] = x + y;
        __syncthreads();
    }
    int incl = sh[threadIdx.x];
    if (gi < n) g_rowptr[gi] = incl - v;
    if (threadIdx.x == 1023) g_bsums[blockIdx.x] = incl;
}

__global__ void k_scanC(int n, int e) {
    __shared__ int sh[128];
    int t = threadIdx.x;
    int nb = (n + 1023) >> 10;
    if (t < 128) sh[t] = (t < nb) ? g_bsums[t] : 0;
    __syncthreads();
    for (int off = 1; off < 128; off <<= 1) {
        int x = 0, y = 0;
        if (t < 128) { x = sh[t]; y = (t >= off) ? sh[t - off] : 0; }
        __syncthreads();
        if (t < 128) sh[t] = x + y;
        __syncthreads();
    }
    int i = blockIdx.x * blockDim.x + t;
    if (i < n) {
        int blk = i >> 10;
        int ex = blk ? sh[blk - 1] : 0;
        int rp = g_rowptr[i] + ex;
        g_rowptr[i] = rp;
        g_cursor[i] = rp;
        g_dinv[i] = rsqrtf((float)(g_cnt[i] + 1));
        g_cnt[i] = 0;
    }
    if (blockIdx.x == 0 && t == 0) g_rowptr[n] = e;
}

__global__ void k_fill(const int* __restrict__ eb, int e) {
    int is64 = detect64(eb);
    int i = blockIdx.x * blockDim.x + threadIdx.x;
    if (i >= e) return;
    int s, d;
    if (is64) { s = eb[2 * i]; d = eb[2 * (e + i)]; }
    else      { s = eb[i];     d = eb[e + i]; }
    int p = atomicAdd(&g_cursor[d], 1);
    g_cedge[p] = make_int2(s, __float_as_int(g_dinv[s]));
}

// ---------------- fused layer kernel: agg -> smem A -> GEMM -> epilogue --
// Per block: 128 nodes. Phase 1: each of 8 warps aggregates 16 nodes
// (O[d] = dinv[d]*(sum_s dinv[s]*X[s] + dinv[d]*X[d])) directly into the
// smem A-tile (fp16). Phase 2: A @ W (W fp16 hi/lo, 2-pass mma), epilogue
// tanh+bias; mode 1 additionally writes fp32 emb and the sigmoid FC head.
__device__ __forceinline__ void acc8(float* a, uint4 u, float w) {
    float2 f;
    f = __half22float2(*(__half2*)&u.x); a[0] += w * f.x; a[1] += w * f.y;
    f = __half22float2(*(__half2*)&u.y); a[2] += w * f.x; a[3] += w * f.y;
    f = __half22float2(*(__half2*)&u.z); a[4] += w * f.x; a[5] += w * f.y;
    f = __half22float2(*(__half2*)&u.w); a[6] += w * f.x; a[7] += w * f.y;
}

__device__ __forceinline__ void mma_f16(float* d, const unsigned* a,
                                        unsigned b0, unsigned b1) {
    asm volatile(
        "mma.sync.aligned.m16n8k16.row.col.f32.f16.f16.f32 "
        "{%0,%1,%2,%3}, {%4,%5,%6,%7}, {%8,%9}, {%0,%1,%2,%3};\n"
        : "+f"(d[0]), "+f"(d[1]), "+f"(d[2]), "+f"(d[3])
        : "r"(a[0]), "r"(a[1]), "r"(a[2]), "r"(a[3]), "r"(b0), "r"(b1));
}

__global__ void __launch_bounds__(256, 2) k_fused(
    const __half* __restrict__ X, const float* __restrict__ W,
    const float* __restrict__ bias,
    __half* __restrict__ outh,                    // mode 0
    float* __restrict__ outf,                     // mode 1: emb
    const float* __restrict__ Wfc, const float* __restrict__ bfc,
    float* __restrict__ fcout,                    // mode 1: fc head
    int n, int mode) {
    extern __shared__ unsigned smu[];
    unsigned* Ahi = smu;
    unsigned* Bhi = Ahi + 128 * KP;
    unsigned* Blo = Bhi + 128 * KP;
    float* sfc = (float*)(Blo + 128 * KP);
    float* sWf = sfc + 128;
    float* sB  = sWf + 128;
    const int tid = threadIdx.x;
    const int wid = tid >> 5, lane = tid & 31;
    const int row0 = blockIdx.x * 128;

    // ---- W[k][n] fp32 -> W^T[n][k] fp16 hi/lo ----
    for (int i = tid; i < 8192; i += 256) {
        int nn_ = i & 127;
        int kp = i >> 7;
        int k = kp * 2;
        float w0 = W[k * DD + nn_];
        float w1 = W[(k + 1) * DD + nn_];
        __half h0 = __float2half_rn(w0), h1 = __float2half_rn(w1);
        __half2 hi = __halves2half2(h0, h1);
        __half2 lo = __floats2half2_rn(w0 - __half2float(h0),
                                       w1 - __half2float(h1));
        Bhi[nn_ * KP + kp] = *(unsigned*)&hi;
        Blo[nn_ * KP + kp] = *(unsigned*)&lo;
    }
    if (tid < 128) {
        sB[tid] = bias[tid];
        sfc[tid] = 0.f;
        if (mode == 1) sWf[tid] = Wfc[tid];
    }

    // ---- phase 1: aggregate 16 nodes per warp into smem A-tile ----
    {
        const int p = lane >> 4, c = lane & 15;
        const uint4* X4 = (const uint4*)X;
        for (int t = 0; t < 16; t++) {
            int r = wid * 16 + t;
            int node = row0 + r;
            if (node >= n) break;
            float di = g_dinv[node];
            float acc[8];
            {
                uint4 u = X4[(size_t)node * 16 + c];
                float w = (p == 0) ? di : 0.f;
                float2 f;
                f = __half22float2(*(__half2*)&u.x); acc[0] = w * f.x; acc[1] = w * f.y;
                f = __half22float2(*(__half2*)&u.y); acc[2] = w * f.x; acc[3] = w * f.y;
                f = __half22float2(*(__half2*)&u.z); acc[4] = w * f.x; acc[5] = w * f.y;
                f = __half22float2(*(__half2*)&u.w); acc[6] = w * f.x; acc[7] = w * f.y;
            }
            int beg = g_rowptr[node];
            int cnt = g_rowptr[node + 1] - beg;
            int done = 0;
            while (done < cnt) {
                int m = cnt - done;
                if (m > 32) m = 32;
                int idx = 0;
                float wv = 0.f;
                if (lane < m) {
                    int2 ew = g_cedge[beg + done + lane];
                    idx = ew.x;
                    wv = __int_as_float(ew.y);
                }
                int j = 0;
                for (; j + 8 <= m; j += 8) {
                    int i0 = __shfl_sync(FULLM, idx, j + p);
                    float w0 = __shfl_sync(FULLM, wv, j + p);
                    int i1 = __shfl_sync(FULLM, idx, j + 2 + p);
                    float w1 = __shfl_sync(FULLM, wv, j + 2 + p);
                    int i2 = __shfl_sync(FULLM, idx, j + 4 + p);
                    float w2 = __shfl_sync(FULLM, wv, j + 4 + p);
                    int i3 = __shfl_sync(FULLM, idx, j + 6 + p);
                    float w3 = __shfl_sync(FULLM, wv, j + 6 + p);
                    uint4 u0 = X4[(size_t)i0 * 16 + c];
                    uint4 u1 = X4[(size_t)i1 * 16 + c];
                    uint4 u2 = X4[(size_t)i2 * 16 + c];
                    uint4 u3 = X4[(size_t)i3 * 16 + c];
                    acc8(acc, u0, w0);
                    acc8(acc, u1, w1);
                    acc8(acc, u2, w2);
                    acc8(acc, u3, w3);
                }
                for (; j + 2 <= m; j += 2) {
                    int i0 = __shfl_sync(FULLM, idx, j + p);
                    float w0 = __shfl_sync(FULLM, wv, j + p);
                    uint4 u0 = X4[(size_t)i0 * 16 + c];
                    acc8(acc, u0, w0);
                }
                if (j < m) {
                    int i0 = __shfl_sync(FULLM, idx, j);
                    float w0 = __shfl_sync(FULLM, wv, j);
                    if (p == 0) {
                        uint4 u0 = X4[(size_t)i0 * 16 + c];
                        acc8(acc, u0, w0);
                    }
                }
                done += m;
            }
#pragma unroll
            for (int k = 0; k < 8; k++)
                acc[k] += __shfl_xor_sync(FULLM, acc[k], 16);
            if (p == 0) {
                __half2 h0 = __floats2half2_rn(di * acc[0], di * acc[1]);
                __half2 h1 = __floats2half2_rn(di * acc[2], di * acc[3]);
                __half2 h2 = __floats2half2_rn(di * acc[4], di * acc[5]);
                __half2 h3 = __floats2half2_rn(di * acc[6], di * acc[7]);
                uint4 u;
                u.x = *(unsigned*)&h0; u.y = *(unsigned*)&h1;
                u.z = *(unsigned*)&h2; u.w = *(unsigned*)&h3;
                *(uint4*)(Ahi + r * KP + 4 * c) = u;
            }
        }
    }
    __syncthreads();

    // ---- phase 2: MMA ----
    const int grp = lane >> 2, tig = lane & 3;
    const int mrow0 = (wid >> 1) * 32;
    const int ncol0 = (wid & 1) * 64;

    float acc[2][8][4];
#pragma unroll
    for (int mi = 0; mi < 2; mi++)
#pragma unroll
        for (int ni = 0; ni < 8; ni++)
#pragma unroll
            for (int q = 0; q < 4; q++) acc[mi][ni][q] = 0.f;

#pragma unroll
    for (int ks = 0; ks < 8; ks++) {
        const int kw = ks * 8 + tig;
        unsigned ah[2][4];
#pragma unroll
        for (int mi = 0; mi < 2; mi++) {
            int r0 = mrow0 + mi * 16 + grp;
            ah[mi][0] = Ahi[r0 * KP + kw];
            ah[mi][1] = Ahi[(r0 + 8) * KP + kw];
            ah[mi][2] = Ahi[r0 * KP + kw + 4];
            ah[mi][3] = Ahi[(r0 + 8) * KP + kw + 4];
        }
#pragma unroll
        for (int ni = 0; ni < 8; ni++) {
            int nr = ncol0 + ni * 8 + grp;
            unsigned bh0 = Bhi[nr * KP + kw], bh1 = Bhi[nr * KP + kw + 4];
            unsigned bl0 = Blo[nr * KP + kw], bl1 = Blo[nr * KP + kw + 4];
#pragma unroll
            for (int mi = 0; mi < 2; mi++) {
                mma_f16(acc[mi][ni], ah[mi], bh0, bh1);
                mma_f16(acc[mi][ni], ah[mi], bl0, bl1);
            }
        }
    }

    // ---- epilogue ----
#pragma unroll
    for (int mi = 0; mi < 2; mi++) {
        int rA = row0 + mrow0 + mi * 16 + grp;
        float pA = 0.f, pB = 0.f;
#pragma unroll
        for (int ni = 0; ni < 8; ni++) {
            int ccol = ncol0 + ni * 8 + tig * 2;
            float bb0 = sB[ccol], bb1 = sB[ccol + 1];
            float v0 = tanhf(acc[mi][ni][0] + bb0);
            float v1 = tanhf(acc[mi][ni][1] + bb1);
            float v2 = tanhf(acc[mi][ni][2] + bb0);
            float v3 = tanhf(acc[mi][ni][3] + bb1);
            if (mode == 0) {
                if (rA < n)
                    *(__half2*)(outh + (size_t)rA * DD + ccol) =
                        __floats2half2_rn(v0, v1);
                if (rA + 8 < n)
                    *(__half2*)(outh + (size_t)(rA + 8) * DD + ccol) =
                        __floats2half2_rn(v2, v3);
            } else {
                if (rA < n)
                    *(float2*)(outf + (size_t)rA * DD + ccol) =
                        make_float2(v0, v1);
                if (rA + 8 < n)
                    *(float2*)(outf + (size_t)(rA + 8) * DD + ccol) =
                        make_float2(v2, v3);
                float wf0 = sWf[ccol], wf1 = sWf[ccol + 1];
                pA += v0 * wf0 + v1 * wf1;
                pB += v2 * wf0 + v3 * wf1;
            }
        }
        if (mode == 1) {
            int rl = mrow0 + mi * 16 + grp;
            if (rA < n) atomicAdd(&sfc[rl], pA);
            if (rA + 8 < n) atomicAdd(&sfc[rl + 8], pB);
        }
    }
    if (mode == 1) {
        __syncthreads();
        if (tid < 128) {
            int r = row0 + tid;
            if (r < n)
                fcout[r] = 1.0f / (1.0f + expf(-(sfc[tid] + bfc[0])));
        }
    }
}

// ---------------- launch ----------------
extern "C" void kernel_launch(void* const* d_in, const int* in_sizes, int n_in,
                              void* d_out, int out_size) {
    const float* x   = (const float*)d_in[0];
    const int*   eb  = (const int*)d_in[1];
    const float* W1  = (const float*)d_in[2];
    const float* b1  = (const float*)d_in[3];
    const float* W2  = (const float*)d_in[4];
    const float* b2  = (const float*)d_in[5];
    const float* Wfc = (const float*)d_in[6];
    const float* bfc = (const float*)d_in[7];

    int n = in_sizes[0] / DD;
    int e = in_sizes[1] / 2;

    float* out = (float*)d_out;
    float* emb = out + n;

    __half *px, *pf;
    cudaGetSymbolAddress((void**)&px, g_x16);
    cudaGetSymbolAddress((void**)&pf, g_f16);

    static cudaStream_t s1 = nullptr;
    static cudaEvent_t evF = nullptr, evP = nullptr;
    static int init_done = 0;
    const int fused_smem = (3 * 128 * KP + 384) * 4;   // 105,984 B
    if (!init_done) {
        cudaFuncSetAttribute(k_fused,
                             cudaFuncAttributeMaxDynamicSharedMemorySize,
                             fused_smem);
        cudaStreamCreateWithFlags(&s1, cudaStreamNonBlocking);
        cudaEventCreateWithFlags(&evF, cudaEventDisableTiming);
        cudaEventCreateWithFlags(&evP, cudaEventDisableTiming);
        init_done = 1;
    }

    const int T = 256;
    int nb = (n + 1023) / 1024;
    int fblocks = (n + 127) / 128;

    // launch 1: x->fp16 on s0 (overlaps preprocessing)
    k_cvt<<<(n * 16 + T - 1) / T, T>>>(x, n * 16);

    // fork preprocessing onto s1
    cudaEventRecord(evF, 0);
    cudaStreamWaitEvent(s1, evF, 0);
    k_hist<<<(e + T - 1) / T, T, 0, s1>>>(eb, e);       // 2
    k_scanA<<<nb, 1024, 0, s1>>>(n);                    // 3
    k_scanC<<<(n + T - 1) / T, T, 0, s1>>>(n, e);       // 4
    k_fill<<<(e + T - 1) / T, T, 0, s1>>>(eb, e);       // 5
    cudaEventRecord(evP, s1);
    cudaStreamWaitEvent(0, evP, 0);

    // layer 1 (fused agg+gemm, launch 6 -> ncu -s 5 profiles this)
    k_fused<<<fblocks, T, fused_smem>>>(px, W1, b1, pf, nullptr, nullptr,
                                        nullptr, nullptr, n, 0);
    // layer 2 (fused agg+gemm + emb + fc head)
    k_fused<<<fblocks, T, fused_smem>>>(pf, W2, b2, nullptr, emb, Wfc, bfc,
                                        out, n, 1);
}

// round 10
// speedup vs baseline: 1.0357x; 1.0357x over previous
#include <cuda_runtime.h>
#include <cuda_fp16.h>
#include <math.h>
#include <stdint.h>

#define NN 100000
#define EE 1600000
#define DD 128
#define KP 68          // padded smem row stride in 32-bit words
#define NCH 4          // layer-2 pipeline chunks
#define FULLM 0xFFFFFFFFu

// ---------------- device scratch (no allocations allowed) ----------------
__device__ int    g_rowptr[NN + 1];
__device__ int    g_cnt[NN];          // zero-init; re-zeroed by k_scanC
__device__ int    g_cursor[NN];
__device__ float  g_dinv[NN];
__device__ int2   g_cedge[EE];        // (src, dinv[src] bits), grouped by dst
__device__ int    g_bsums[128];
__device__ __half g_h16[(size_t)NN * DD];  // h = X @ W1 (fp16)
__device__ __half g_f16[(size_t)NN * DD];  // layer-1 activations f
__device__ __half g_ax[(size_t)NN * DD];   // layer-2 aggregated rows

// ---------------- edge dtype detection (per warp) ----------------
__device__ __forceinline__ int detect64(const int* __restrict__ eb) {
    unsigned nz = 0;
#pragma unroll
    for (int i = (threadIdx.x & 31); i < 128; i += 32)
        nz |= (eb[2 * i + 1] != 0);
    return __ballot_sync(FULLM, nz) == 0;
}

// ---------------- preprocessing (R7 formulation — fastest measured) ------
__global__ void k_hist(const int* __restrict__ eb, int e) {
    int is64 = detect64(eb);
    int i = blockIdx.x * blockDim.x + threadIdx.x;
    if (i >= e) return;
    int d = is64 ? eb[2 * (e + i)] : eb[e + i];
    atomicAdd(&g_cnt[d], 1);
}

__global__ void k_scanA(int n) {
    __shared__ int sh[1024];
    int gi = blockIdx.x * 1024 + threadIdx.x;
    int v = (gi < n) ? g_cnt[gi] : 0;
    sh[threadIdx.x] = v;
    __syncthreads();
    for (int off = 1; off < 1024; off <<= 1) {
        int x = sh[threadIdx.x];
        int y = (threadIdx.x >= off) ? sh[threadIdx.x - off] : 0;
        __syncthreads();
        sh[threadIdx.x] = x + y;
        __syncthreads();
    }
    int incl = sh[threadIdx.x];
    if (gi < n) g_rowptr[gi] = incl - v;
    if (threadIdx.x == 1023) g_bsums[blockIdx.x] = incl;
}

__global__ void k_scanC(int n, int e) {
    __shared__ int sh[128];
    int t = threadIdx.x;
    int nb = (n + 1023) >> 10;
    if (t < 128) sh[t] = (t < nb) ? g_bsums[t] : 0;
    __syncthreads();
    for (int off = 1; off < 128; off <<= 1) {
        int x = 0, y = 0;
        if (t < 128) { x = sh[t]; y = (t >= off) ? sh[t - off] : 0; }
        __syncthreads();
        if (t < 128) sh[t] = x + y;
        __syncthreads();
    }
    int i = blockIdx.x * blockDim.x + t;
    if (i < n) {
        int blk = i >> 10;
        int ex = blk ? sh[blk - 1] : 0;
        int rp = g_rowptr[i] + ex;
        g_rowptr[i] = rp;
        g_cursor[i] = rp;
        g_dinv[i] = rsqrtf((float)(g_cnt[i] + 1));
        g_cnt[i] = 0;
    }
    if (blockIdx.x == 0 && t == 0) g_rowptr[n] = e;
}

__global__ void k_fill(const int* __restrict__ eb, int e) {
    int is64 = detect64(eb);
    int i = blockIdx.x * blockDim.x + threadIdx.x;
    if (i >= e) return;
    int s, d;
    if (is64) { s = eb[2 * i]; d = eb[2 * (e + i)]; }
    else      { s = eb[i];     d = eb[e + i]; }
    int p = atomicAdd(&g_cursor[d], 1);
    g_cedge[p] = make_int2(s, __float_as_int(g_dinv[s]));
}

// ---------------- shared gather helpers ----------------
__device__ __forceinline__ void acc8(float* a, uint4 u, float w) {
    float2 f;
    f = __half22float2(*(__half2*)&u.x); a[0] += w * f.x; a[1] += w * f.y;
    f = __half22float2(*(__half2*)&u.y); a[2] += w * f.x; a[3] += w * f.y;
    f = __half22float2(*(__half2*)&u.z); a[4] += w * f.x; a[5] += w * f.y;
    f = __half22float2(*(__half2*)&u.w); a[6] += w * f.x; a[7] += w * f.y;
}

// core gather: acc = dinv[node]*X[node] (slot0) + sum_edges dinv[s]*X[s]
__device__ __forceinline__ void gather_node(const uint4* __restrict__ X4,
                                            int node, int lane, int p, int c,
                                            float di, float* acc) {
    {
        uint4 u = X4[(size_t)node * 16 + c];
        float w = (p == 0) ? di : 0.f;
        float2 f;
        f = __half22float2(*(__half2*)&u.x); acc[0] = w * f.x; acc[1] = w * f.y;
        f = __half22float2(*(__half2*)&u.y); acc[2] = w * f.x; acc[3] = w * f.y;
        f = __half22float2(*(__half2*)&u.z); acc[4] = w * f.x; acc[5] = w * f.y;
        f = __half22float2(*(__half2*)&u.w); acc[6] = w * f.x; acc[7] = w * f.y;
    }
    int beg = g_rowptr[node];
    int cnt = g_rowptr[node + 1] - beg;
    int done = 0;
    while (done < cnt) {
        int m = cnt - done;
        if (m > 32) m = 32;
        int idx = 0;
        float wv = 0.f;
        if (lane < m) {
            int2 ew = g_cedge[beg + done + lane];
            idx = ew.x;
            wv = __int_as_float(ew.y);
        }
        int j = 0;
        for (; j + 8 <= m; j += 8) {
            int i0 = __shfl_sync(FULLM, idx, j + p);
            float w0 = __shfl_sync(FULLM, wv, j + p);
            int i1 = __shfl_sync(FULLM, idx, j + 2 + p);
            float w1 = __shfl_sync(FULLM, wv, j + 2 + p);
            int i2 = __shfl_sync(FULLM, idx, j + 4 + p);
            float w2 = __shfl_sync(FULLM, wv, j + 4 + p);
            int i3 = __shfl_sync(FULLM, idx, j + 6 + p);
            float w3 = __shfl_sync(FULLM, wv, j + 6 + p);
            uint4 u0 = X4[(size_t)i0 * 16 + c];
            uint4 u1 = X4[(size_t)i1 * 16 + c];
            uint4 u2 = X4[(size_t)i2 * 16 + c];
            uint4 u3 = X4[(size_t)i3 * 16 + c];
            acc8(acc, u0, w0);
            acc8(acc, u1, w1);
            acc8(acc, u2, w2);
            acc8(acc, u3, w3);
        }
        for (; j + 2 <= m; j += 2) {
            int i0 = __shfl_sync(FULLM, idx, j + p);
            float w0 = __shfl_sync(FULLM, wv, j + p);
            uint4 u0 = X4[(size_t)i0 * 16 + c];
            acc8(acc, u0, w0);
        }
        if (j < m) {
            int i0 = __shfl_sync(FULLM, idx, j);
            float w0 = __shfl_sync(FULLM, wv, j);
            if (p == 0) {
                uint4 u0 = X4[(size_t)i0 * 16 + c];
                acc8(acc, u0, w0);
            }
        }
        done += m;
    }
#pragma unroll
    for (int k = 0; k < 8; k++)
        acc[k] += __shfl_xor_sync(FULLM, acc[k], 16);
}

// layer-1 aggregation with fused tanh+bias: f = tanh(dinv*agg(h) + b) -> fp16
__global__ void __launch_bounds__(256) k_agg_act(const __half* __restrict__ H,
                                                 const float* __restrict__ b,
                                                 __half* __restrict__ O, int n) {
    int node = (blockIdx.x * blockDim.x + threadIdx.x) >> 5;
    int lane = threadIdx.x & 31;
    if (node >= n) return;
    int p = lane >> 4, c = lane & 15;
    float di = g_dinv[node];
    float acc[8];
    gather_node((const uint4*)H, node, lane, p, c, di, acc);
    if (p == 0) {
        float4 b0 = ((const float4*)b)[c * 2];
        float4 b1 = ((const float4*)b)[c * 2 + 1];
        __half2 h0 = __floats2half2_rn(tanhf(di * acc[0] + b0.x),
                                       tanhf(di * acc[1] + b0.y));
        __half2 h1 = __floats2half2_rn(tanhf(di * acc[2] + b0.z),
                                       tanhf(di * acc[3] + b0.w));
        __half2 h2 = __floats2half2_rn(tanhf(di * acc[4] + b1.x),
                                       tanhf(di * acc[5] + b1.y));
        __half2 h3 = __floats2half2_rn(tanhf(di * acc[6] + b1.z),
                                       tanhf(di * acc[7] + b1.w));
        uint4 u;
        u.x = *(unsigned*)&h0; u.y = *(unsigned*)&h1;
        u.z = *(unsigned*)&h2; u.w = *(unsigned*)&h3;
        ((uint4*)O)[(size_t)node * 16 + c] = u;
    }
}

// layer-2 plain aggregation: O = dinv*agg(f) -> fp16 (feeds gemm2)
__global__ void __launch_bounds__(256) k_agg(const __half* __restrict__ X,
                                             __half* __restrict__ O,
                                             int n0, int n1) {
    int node = n0 + ((blockIdx.x * blockDim.x + threadIdx.x) >> 5);
    int lane = threadIdx.x & 31;
    if (node >= n1) return;
    int p = lane >> 4, c = lane & 15;
    float di = g_dinv[node];
    float acc[8];
    gather_node((const uint4*)X, node, lane, p, c, di, acc);
    if (p == 0) {
        __half2 h0 = __floats2half2_rn(di * acc[0], di * acc[1]);
        __half2 h1 = __floats2half2_rn(di * acc[2], di * acc[3]);
        __half2 h2 = __floats2half2_rn(di * acc[4], di * acc[5]);
        __half2 h3 = __floats2half2_rn(di * acc[6], di * acc[7]);
        uint4 u;
        u.x = *(unsigned*)&h0; u.y = *(unsigned*)&h1;
        u.z = *(unsigned*)&h2; u.w = *(unsigned*)&h3;
        ((uint4*)O)[(size_t)node * 16 + c] = u;
    }
}

// ---------------- GEMMs ----------------
__device__ __forceinline__ void mma_f16(float* d, const unsigned* a,
                                        unsigned b0, unsigned b1) {
    asm volatile(
        "mma.sync.aligned.m16n8k16.row.col.f32.f16.f16.f32 "
        "{%0,%1,%2,%3}, {%4,%5,%6,%7}, {%8,%9}, {%0,%1,%2,%3};\n"
        : "+f"(d[0]), "+f"(d[1]), "+f"(d[2]), "+f"(d[3])
        : "r"(a[0]), "r"(a[1]), "r"(a[2]), "r"(a[3]), "r"(b0), "r"(b1));
}

// gemm1: h = X(fp32) @ W1, 3-pass hi/lo, raw fp16 output. Runs under preproc.
__global__ void __launch_bounds__(256) k_gemm1(const float* __restrict__ A,
                                               const float* __restrict__ W,
                                               __half* __restrict__ C, int n) {
    extern __shared__ unsigned smu[];
    unsigned* Ahi = smu;
    unsigned* Alo = Ahi + 128 * KP;
    unsigned* Bhi = Alo + 128 * KP;
    unsigned* Blo = Bhi + 128 * KP;
    const int tid = threadIdx.x;
    const int row0 = blockIdx.x * 128;

    for (int i = tid; i < 8192; i += 256) {
        int nn_ = i & 127;
        int kp = i >> 7;
        int k = kp * 2;
        float w0 = W[k * DD + nn_];
        float w1 = W[(k + 1) * DD + nn_];
        __half h0 = __float2half_rn(w0), h1 = __float2half_rn(w1);
        __half2 hi = __halves2half2(h0, h1);
        __half2 lo = __floats2half2_rn(w0 - __half2float(h0),
                                       w1 - __half2float(h1));
        Bhi[nn_ * KP + kp] = *(unsigned*)&hi;
        Blo[nn_ * KP + kp] = *(unsigned*)&lo;
    }
    {
        const float4* A4 = (const float4*)A;
        for (int i = tid; i < 4096; i += 256) {
            int r = i >> 5, j = i & 31;
            float4 v = make_float4(0.f, 0.f, 0.f, 0.f);
            if (row0 + r < n) v = A4[(size_t)(row0 + r) * 32 + j];
            __half2 h01 = __floats2half2_rn(v.x, v.y);
            __half2 h23 = __floats2half2_rn(v.z, v.w);
            float2 f01 = __half22float2(h01);
            float2 f23 = __half22float2(h23);
            __half2 l01 = __floats2half2_rn(v.x - f01.x, v.y - f01.y);
            __half2 l23 = __floats2half2_rn(v.z - f23.x, v.w - f23.y);
            *(uint2*)(Ahi + r * KP + 2 * j) =
                make_uint2(*(unsigned*)&h01, *(unsigned*)&h23);
            *(uint2*)(Alo + r * KP + 2 * j) =
                make_uint2(*(unsigned*)&l01, *(unsigned*)&l23);
        }
    }
    __syncthreads();

    const int wid = tid >> 5, lane = tid & 31;
    const int grp = lane >> 2, tig = lane & 3;
    const int mrow0 = (wid >> 1) * 32;
    const int ncol0 = (wid & 1) * 64;

    float acc[2][8][4];
#pragma unroll
    for (int mi = 0; mi < 2; mi++)
#pragma unroll
        for (int ni = 0; ni < 8; ni++)
#pragma unroll
            for (int q = 0; q < 4; q++) acc[mi][ni][q] = 0.f;

#pragma unroll
    for (int ks = 0; ks < 8; ks++) {
        const int kw = ks * 8 + tig;
        unsigned ah[2][4], al[2][4];
#pragma unroll
        for (int mi = 0; mi < 2; mi++) {
            int r0 = mrow0 + mi * 16 + grp;
            ah[mi][0] = Ahi[r0 * KP + kw];
            ah[mi][1] = Ahi[(r0 + 8) * KP + kw];
            ah[mi][2] = Ahi[r0 * KP + kw + 4];
            ah[mi][3] = Ahi[(r0 + 8) * KP + kw + 4];
            al[mi][0] = Alo[r0 * KP + kw];
            al[mi][1] = Alo[(r0 + 8) * KP + kw];
            al[mi][2] = Alo[r0 * KP + kw + 4];
            al[mi][3] = Alo[(r0 + 8) * KP + kw + 4];
        }
#pragma unroll
        for (int ni = 0; ni < 8; ni++) {
            int nr = ncol0 + ni * 8 + grp;
            unsigned bh0 = Bhi[nr * KP + kw], bh1 = Bhi[nr * KP + kw + 4];
            unsigned bl0 = Blo[nr * KP + kw], bl1 = Blo[nr * KP + kw + 4];
#pragma unroll
            for (int mi = 0; mi < 2; mi++) {
                mma_f16(acc[mi][ni], ah[mi], bh0, bh1);
                mma_f16(acc[mi][ni], ah[mi], bl0, bl1);
                mma_f16(acc[mi][ni], al[mi], bh0, bh1);
            }
        }
    }

#pragma unroll
    for (int mi = 0; mi < 2; mi++) {
        int r = row0 + mrow0 + mi * 16 + grp;
#pragma unroll
        for (int ni = 0; ni < 8; ni++) {
            int c = ncol0 + ni * 8 + tig * 2;
            if (r < n)
                *(__half2*)(C + (size_t)r * DD + c) =
                    __floats2half2_rn(acc[mi][ni][0], acc[mi][ni][1]);
            if (r + 8 < n)
                *(__half2*)(C + (size_t)(r + 8) * DD + c) =
                    __floats2half2_rn(acc[mi][ni][2], acc[mi][ni][3]);
        }
    }
}

// gemm2: emb = tanh(A @ W2 + b2) (fp32 out) + fused sigmoid FC head.
// A fp16 exact -> 2-pass.
__global__ void __launch_bounds__(256) k_gemm2(
    const __half* __restrict__ A, const float* __restrict__ W,
    const float* __restrict__ bias, float* __restrict__ outf,
    const float* __restrict__ Wfc, const float* __restrict__ bfc,
    float* __restrict__ fcout, int n0, int n) {
    extern __shared__ unsigned smu[];
    unsigned* Ahi = smu;
    unsigned* Bhi = Ahi + 128 * KP;
    unsigned* Blo = Bhi + 128 * KP;
    float* sfc = (float*)(Blo + 128 * KP);
    float* sWf = sfc + 128;
    float* sB  = sWf + 128;
    const int tid = threadIdx.x;
    const int row0 = n0 + blockIdx.x * 128;

    for (int i = tid; i < 8192; i += 256) {
        int nn_ = i & 127;
        int kp = i >> 7;
        int k = kp * 2;
        float w0 = W[k * DD + nn_];
        float w1 = W[(k + 1) * DD + nn_];
        __half h0 = __float2half_rn(w0), h1 = __float2half_rn(w1);
        __half2 hi = __halves2half2(h0, h1);
        __half2 lo = __floats2half2_rn(w0 - __half2float(h0),
                                       w1 - __half2float(h1));
        Bhi[nn_ * KP + kp] = *(unsigned*)&hi;
        Blo[nn_ * KP + kp] = *(unsigned*)&lo;
    }
    {
        const uint4* A4 = (const uint4*)A;
        for (int i = tid; i < 2048; i += 256) {
            int r = i >> 4, j = i & 15;
            uint4 u = make_uint4(0, 0, 0, 0);
            if (row0 + r < n) u = A4[(size_t)(row0 + r) * 16 + j];
            *(uint4*)(Ahi + r * KP + 4 * j) = u;
        }
    }
    if (tid < 128) {
        sB[tid] = bias[tid];
        sfc[tid] = 0.f;
        sWf[tid] = Wfc[tid];
    }
    __syncthreads();

    const int wid = tid >> 5, lane = tid & 31;
    const int grp = lane >> 2, tig = lane & 3;
    const int mrow0 = (wid >> 1) * 32;
    const int ncol0 = (wid & 1) * 64;

    float acc[2][8][4];
#pragma unroll
    for (int mi = 0; mi < 2; mi++)
#pragma unroll
        for (int ni = 0; ni < 8; ni++)
#pragma unroll
            for (int q = 0; q < 4; q++) acc[mi][ni][q] = 0.f;

#pragma unroll
    for (int ks = 0; ks < 8; ks++) {
        const int kw = ks * 8 + tig;
        unsigned ah[2][4];
#pragma unroll
        for (int mi = 0; mi < 2; mi++) {
            int r0 = mrow0 + mi * 16 + grp;
            ah[mi][0] = Ahi[r0 * KP + kw];
            ah[mi][1] = Ahi[(r0 + 8) * KP + kw];
            ah[mi][2] = Ahi[r0 * KP + kw + 4];
            ah[mi][3] = Ahi[(r0 + 8) * KP + kw + 4];
        }
#pragma unroll
        for (int ni = 0; ni < 8; ni++) {
            int nr = ncol0 + ni * 8 + grp;
            unsigned bh0 = Bhi[nr * KP + kw], bh1 = Bhi[nr * KP + kw + 4];
            unsigned bl0 = Blo[nr * KP + kw], bl1 = Blo[nr * KP + kw + 4];
#pragma unroll
            for (int mi = 0; mi < 2; mi++) {
                mma_f16(acc[mi][ni], ah[mi], bh0, bh1);
                mma_f16(acc[mi][ni], ah[mi], bl0, bl1);
            }
        }
    }

#pragma unroll
    for (int mi = 0; mi < 2; mi++) {
        int rA = row0 + mrow0 + mi * 16 + grp;
        float pA = 0.f, pB = 0.f;
#pragma unroll
        for (int ni = 0; ni < 8; ni++) {
            int ccol = ncol0 + ni * 8 + tig * 2;
            float bb0 = sB[ccol], bb1 = sB[ccol + 1];
            float v0 = tanhf(acc[mi][ni][0] + bb0);
            float v1 = tanhf(acc[mi][ni][1] + bb1);
            float v2 = tanhf(acc[mi][ni][2] + bb0);
            float v3 = tanhf(acc[mi][ni][3] + bb1);
            if (rA < n)
                *(float2*)(outf + (size_t)rA * DD + ccol) =
                    make_float2(v0, v1);
            if (rA + 8 < n)
                *(float2*)(outf + (size_t)(rA + 8) * DD + ccol) =
                    make_float2(v2, v3);
            float wf0 = sWf[ccol], wf1 = sWf[ccol + 1];
            pA += v0 * wf0 + v1 * wf1;
            pB += v2 * wf0 + v3 * wf1;
        }
        int rl = mrow0 + mi * 16 + grp;
        if (rA < n) atomicAdd(&sfc[rl], pA);
        if (rA + 8 < n) atomicAdd(&sfc[rl + 8], pB);
    }
    __syncthreads();
    if (tid < 128) {
        int r = row0 + tid;
        if (r < n)
            fcout[r] = 1.0f / (1.0f + expf(-(sfc[tid] + bfc[0])));
    }
}

// ---------------- launch ----------------
extern "C" void kernel_launch(void* const* d_in, const int* in_sizes, int n_in,
                              void* d_out, int out_size) {
    const float* x   = (const float*)d_in[0];
    const int*   eb  = (const int*)d_in[1];
    const float* W1  = (const float*)d_in[2];
    const float* b1  = (const float*)d_in[3];
    const float* W2  = (const float*)d_in[4];
    const float* b2  = (const float*)d_in[5];
    const float* Wfc = (const float*)d_in[6];
    const float* bfc = (const float*)d_in[7];

    int n = in_sizes[0] / DD;
    int e = in_sizes[1] / 2;

    float* out = (float*)d_out;
    float* emb = out + n;

    __half *ph, *pf, *pa;
    cudaGetSymbolAddress((void**)&ph, g_h16);
    cudaGetSymbolAddress((void**)&pf, g_f16);
    cudaGetSymbolAddress((void**)&pa, g_ax);

    static cudaStream_t s1 = nullptr, s2 = nullptr;
    static cudaEvent_t evF = nullptr, evP = nullptr, evL = nullptr, evB[NCH];
    static int init_done = 0;
    const int g1_smem = 4 * 128 * KP * 4;            // 139,264 B
    const int g2_smem = (3 * 128 * KP + 384) * 4;    // 105,984 B
    if (!init_done) {
        cudaFuncSetAttribute(k_gemm1,
                             cudaFuncAttributeMaxDynamicSharedMemorySize,
                             g1_smem);
        cudaFuncSetAttribute(k_gemm2,
                             cudaFuncAttributeMaxDynamicSharedMemorySize,
                             g2_smem);
        cudaStreamCreateWithFlags(&s1, cudaStreamNonBlocking);
        cudaStreamCreateWithFlags(&s2, cudaStreamNonBlocking);
        cudaEventCreateWithFlags(&evF, cudaEventDisableTiming);
        cudaEventCreateWithFlags(&evP, cudaEventDisableTiming);
        cudaEventCreateWithFlags(&evL, cudaEventDisableTiming);
        for (int c = 0; c < NCH; c++)
            cudaEventCreateWithFlags(&evB[c], cudaEventDisableTiming);
        init_done = 1;
    }

    const int T = 256;
    int nb = (n + 1023) / 1024;
    int gblocks = (n + 127) / 128;
    int chunk = (((n + NCH - 1) / NCH) + 127) & ~127;

    // fork: preprocessing on s1 starts immediately (before gemm1 queues)
    cudaEventRecord(evF, 0);
    cudaStreamWaitEvent(s1, evF, 0);
    k_hist<<<(e + T - 1) / T, T, 0, s1>>>(eb, e);
    k_scanA<<<nb, 1024, 0, s1>>>(n);
    k_scanC<<<(n + T - 1) / T, T, 0, s1>>>(n, e);
    k_fill<<<(e + T - 1) / T, T, 0, s1>>>(eb, e);
    cudaEventRecord(evP, s1);

    // gemm1 on s0, fully overlapped with preprocessing
    k_gemm1<<<gblocks, 256, g1_smem>>>(x, W1, ph, n);

    cudaStreamWaitEvent(0, evP, 0);

    // layer 1: single full-width aggregation with fused tanh+bias
    k_agg_act<<<(n * 32 + T - 1) / T, T>>>(ph, b1, pf, n);

    // layer 2: agg chunks pipelined with gemm2 (+emb+fc head)
    for (int c = 0; c < NCH; c++) {
        int c0 = c * chunk, c1 = min(n, c0 + chunk);
        if (c0 >= n) break;
        int nodes = c1 - c0;
        k_agg<<<(nodes * 32 + T - 1) / T, T>>>(pf, pa, c0, c1);
        cudaEventRecord(evB[c], 0);
        cudaStreamWaitEvent(s2, evB[c], 0);
        k_gemm2<<<(nodes + 127) / 128, 256, g2_smem, s2>>>(
            pa, W2, b2, emb, Wfc, bfc, out, c0, n);
    }
    cudaEventRecord(evL, s2);
    cudaStreamWaitEvent(0, evL, 0);
}

// round 13
// speedup vs baseline: 1.1234x; 1.0847x over previous
#include <cuda_runtime.h>
#include <cuda_fp16.h>
#include <math.h>
#include <stdint.h>

#define NN 100000
#define EE 1600000
#define DD 128
#define KP 68          // padded smem row stride in 32-bit words
#define NCH 4          // pipeline chunks
#define FULLM 0xFFFFFFFFu

// ---------------- device scratch (no allocations allowed) ----------------
__device__ int    g_rowptr[NN + 1];
__device__ int    g_cnt[NN];          // zero-init; re-zeroed by k_scanC
__device__ int    g_cursor[NN];
__device__ float  g_dinv[NN];
__device__ int2   g_cedge[EE];        // (src, dinv[src] bits), grouped by dst
__device__ int    g_bsums[128];
__device__ __align__(256) __half g_x16[(size_t)NN * DD];  // fp16 input x
__device__ __align__(256) __half g_ax[(size_t)NN * DD];   // aggregated rows
__device__ __align__(256) __half g_f16[(size_t)NN * DD];  // layer-1 acts

// ---------------- L2 residency helpers (v8.b32 = 32 B, required width) ----
__device__ __forceinline__ void ldg_keep8(const unsigned* p, unsigned* u) {
    asm volatile(
        "ld.global.nc.L2::evict_last.v8.b32 {%0,%1,%2,%3,%4,%5,%6,%7}, [%8];"
        : "=r"(u[0]), "=r"(u[1]), "=r"(u[2]), "=r"(u[3]),
          "=r"(u[4]), "=r"(u[5]), "=r"(u[6]), "=r"(u[7])
        : "l"(p));
}
__device__ __forceinline__ void ldg_stream8(const unsigned* p, unsigned* u) {
    asm volatile(
        "ld.global.nc.L2::evict_first.v8.b32 {%0,%1,%2,%3,%4,%5,%6,%7}, [%8];"
        : "=r"(u[0]), "=r"(u[1]), "=r"(u[2]), "=r"(u[3]),
          "=r"(u[4]), "=r"(u[5]), "=r"(u[6]), "=r"(u[7])
        : "l"(p));
}

// ---------------- x -> fp16 ----------------
__global__ void k_cvt(const float* __restrict__ x, int total8) {
    int i = blockIdx.x * blockDim.x + threadIdx.x;
    if (i >= total8) return;
    unsigned u[8];
    ldg_stream8((const unsigned*)x + (size_t)i * 8, u);
    uint4 o;
    __half2 h;
    h = __floats2half2_rn(__uint_as_float(u[0]), __uint_as_float(u[1]));
    o.x = *(unsigned*)&h;
    h = __floats2half2_rn(__uint_as_float(u[2]), __uint_as_float(u[3]));
    o.y = *(unsigned*)&h;
    h = __floats2half2_rn(__uint_as_float(u[4]), __uint_as_float(u[5]));
    o.z = *(unsigned*)&h;
    h = __floats2half2_rn(__uint_as_float(u[6]), __uint_as_float(u[7]));
    o.w = *(unsigned*)&h;
    ((uint4*)g_x16)[i] = o;
}

// ---------------- edge dtype detection (per warp) ----------------
__device__ __forceinline__ int detect64(const int* __restrict__ eb) {
    unsigned nz = 0;
#pragma unroll
    for (int i = (threadIdx.x & 31); i < 128; i += 32)
        nz |= (eb[2 * i + 1] != 0);
    return __ballot_sync(FULLM, nz) == 0;
}

// ---------------- preprocessing (R7 formulation — fastest measured) ------
__global__ void k_hist(const int* __restrict__ eb, int e) {
    int is64 = detect64(eb);
    int i = blockIdx.x * blockDim.x + threadIdx.x;
    if (i >= e) return;
    int d = is64 ? eb[2 * (e + i)] : eb[e + i];
    atomicAdd(&g_cnt[d], 1);
}

__global__ void k_scanA(int n) {
    __shared__ int sh[1024];
    int gi = blockIdx.x * 1024 + threadIdx.x;
    int v = (gi < n) ? g_cnt[gi] : 0;
    sh[threadIdx.x] = v;
    __syncthreads();
    for (int off = 1; off < 1024; off <<= 1) {
        int x = sh[threadIdx.x];
        int y = (threadIdx.x >= off) ? sh[threadIdx.x - off] : 0;
        __syncthreads();
        sh[threadIdx.x] = x + y;
        __syncthreads();
    }
    int incl = sh[threadIdx.x];
    if (gi < n) g_rowptr[gi] = incl - v;
    if (threadIdx.x == 1023) g_bsums[blockIdx.x] = incl;
}

__global__ void k_scanC(int n, int e) {
    __shared__ int sh[128];
    int t = threadIdx.x;
    int nb = (n + 1023) >> 10;
    if (t < 128) sh[t] = (t < nb) ? g_bsums[t] : 0;
    __syncthreads();
    for (int off = 1; off < 128; off <<= 1) {
        int x = 0, y = 0;
        if (t < 128) { x = sh[t]; y = (t >= off) ? sh[t - off] : 0; }
        __syncthreads();
        if (t < 128) sh[t] = x + y;
        __syncthreads();
    }
    int i = blockIdx.x * blockDim.x + t;
    if (i < n) {
        int blk = i >> 10;
        int ex = blk ? sh[blk - 1] : 0;
        int rp = g_rowptr[i] + ex;
        g_rowptr[i] = rp;
        g_cursor[i] = rp;
        g_dinv[i] = rsqrtf((float)(g_cnt[i] + 1));
        g_cnt[i] = 0;
    }
    if (blockIdx.x == 0 && t == 0) g_rowptr[n] = e;
}

__global__ void k_fill(const int* __restrict__ eb, int e) {
    int is64 = detect64(eb);
    int i = blockIdx.x * blockDim.x + threadIdx.x;
    if (i >= e) return;
    int s, d;
    if (is64) { s = eb[2 * i]; d = eb[2 * (e + i)]; }
    else      { s = eb[i];     d = eb[e + i]; }
    int p = atomicAdd(&g_cursor[d], 1);
    g_cedge[p] = make_int2(s, __float_as_int(g_dinv[s]));
}

// ---------------- aggregation: O[d] = dinv[d]*(sum_s dinv[s]*X[s] + dinv[d]*X[d])
// Warp = 4 edge-slots x 8 lanes; each lane owns 16 features (32 B, v8 load,
// L2 evict_last to pin the gather table).
__device__ __forceinline__ void acc16(float* a, const unsigned* u, float w) {
#pragma unroll
    for (int q = 0; q < 8; q++) {
        float2 f = __half22float2(*(__half2*)&u[q]);
        a[2 * q] += w * f.x;
        a[2 * q + 1] += w * f.y;
    }
}

__global__ void __launch_bounds__(256) k_agg16(
    const __half* __restrict__ H,
    __half* __restrict__ outh, int n0, int n1) {
    int node = n0 + ((blockIdx.x * blockDim.x + threadIdx.x) >> 5);
    int lane = threadIdx.x & 31;
    if (node >= n1) return;
    int p = lane >> 3, c = lane & 7;          // slot, 32B-chunk
    const unsigned* Hb = (const unsigned*)H;  // row = 64 unsigned
    float di = g_dinv[node];

    float acc[16];
    {
        unsigned u[8];
        ldg_keep8(Hb + (size_t)node * 64 + c * 8, u);
        float w = (p == 0) ? di : 0.f;
#pragma unroll
        for (int q = 0; q < 8; q++) {
            float2 f = __half22float2(*(__half2*)&u[q]);
            acc[2 * q] = w * f.x;
            acc[2 * q + 1] = w * f.y;
        }
    }

    int beg = g_rowptr[node];
    int cnt = g_rowptr[node + 1] - beg;
    int done = 0;
    while (done < cnt) {
        int m = cnt - done;
        if (m > 32) m = 32;
        int idx = 0;
        float wv = 0.f;
        if (lane < m) {
            int2 ew = g_cedge[beg + done + lane];
            idx = ew.x;
            wv = __int_as_float(ew.y);
        }
        int j = 0;
        for (; j + 8 <= m; j += 8) {
            int e0 = j + p, e1 = j + 4 + p;
            int i0 = __shfl_sync(FULLM, idx, e0);
            float w0 = __shfl_sync(FULLM, wv, e0);
            int i1 = __shfl_sync(FULLM, idx, e1);
            float w1 = __shfl_sync(FULLM, wv, e1);
            unsigned u0[8], u1[8];
            ldg_keep8(Hb + (size_t)i0 * 64 + c * 8, u0);
            ldg_keep8(Hb + (size_t)i1 * 64 + c * 8, u1);
            acc16(acc, u0, w0);
            acc16(acc, u1, w1);
        }
        for (; j < m; j += 4) {
            int e = j + p;
            int sel = e & 31;
            int i0 = __shfl_sync(FULLM, idx, sel);
            float w0 = __shfl_sync(FULLM, wv, sel);
            if (e < m) {
                unsigned u0[8];
                ldg_keep8(Hb + (size_t)i0 * 64 + c * 8, u0);
                acc16(acc, u0, w0);
            }
        }
        done += m;
    }

    // reduce across the 4 slots (lane bits 3,4)
#pragma unroll
    for (int k = 0; k < 16; k++) {
        acc[k] += __shfl_xor_sync(FULLM, acc[k], 8);
        acc[k] += __shfl_xor_sync(FULLM, acc[k], 16);
    }

    if (p == 0) {
        uint4 oA, oB;
        __half2 h;
        h = __floats2half2_rn(di * acc[0], di * acc[1]);  oA.x = *(unsigned*)&h;
        h = __floats2half2_rn(di * acc[2], di * acc[3]);  oA.y = *(unsigned*)&h;
        h = __floats2half2_rn(di * acc[4], di * acc[5]);  oA.z = *(unsigned*)&h;
        h = __floats2half2_rn(di * acc[6], di * acc[7]);  oA.w = *(unsigned*)&h;
        h = __floats2half2_rn(di * acc[8], di * acc[9]);  oB.x = *(unsigned*)&h;
        h = __floats2half2_rn(di * acc[10], di * acc[11]); oB.y = *(unsigned*)&h;
        h = __floats2half2_rn(di * acc[12], di * acc[13]); oB.z = *(unsigned*)&h;
        h = __floats2half2_rn(di * acc[14], di * acc[15]); oB.w = *(unsigned*)&h;
        ((uint4*)outh)[(size_t)node * 16 + c * 2] = oA;
        ((uint4*)outh)[(size_t)node * 16 + c * 2 + 1] = oB;
    }
}

// ---------------- GEMM + fused activation epilogue ----------------
__device__ __forceinline__ void mma_f16(float* d, const unsigned* a,
                                        unsigned b0, unsigned b1) {
    asm volatile(
        "mma.sync.aligned.m16n8k16.row.col.f32.f16.f16.f32 "
        "{%0,%1,%2,%3}, {%4,%5,%6,%7}, {%8,%9}, {%0,%1,%2,%3};\n"
        : "+f"(d[0]), "+f"(d[1]), "+f"(d[2]), "+f"(d[3])
        : "r"(a[0]), "r"(a[1]), "r"(a[2]), "r"(a[3]), "r"(b0), "r"(b1));
}

__global__ void __launch_bounds__(256) k_gemm(
    const __half* __restrict__ A, const float* __restrict__ W,
    const float* __restrict__ bias,
    __half* __restrict__ outh,                    // mode 0
    float* __restrict__ outf,                     // mode 1: emb
    const float* __restrict__ Wfc, const float* __restrict__ bfc,
    float* __restrict__ fcout,                    // mode 1: fc head
    int n0, int n, int mode) {
    extern __shared__ unsigned smu[];
    unsigned* Ahi = smu;
    unsigned* Bhi = Ahi + 128 * KP;
    unsigned* Blo = Bhi + 128 * KP;
    float* sfc = (float*)(Blo + 128 * KP);
    float* sWf = sfc + 128;
    float* sB  = sWf + 128;
    const int tid = threadIdx.x;
    const int row0 = n0 + blockIdx.x * 128;

    for (int i = tid; i < 8192; i += 256) {
        int nn_ = i & 127;
        int kp = i >> 7;
        int k = kp * 2;
        float w0 = W[k * DD + nn_];
        float w1 = W[(k + 1) * DD + nn_];
        __half h0 = __float2half_rn(w0), h1 = __float2half_rn(w1);
        __half2 hi = __halves2half2(h0, h1);
        __half2 lo = __floats2half2_rn(w0 - __half2float(h0),
                                       w1 - __half2float(h1));
        Bhi[nn_ * KP + kp] = *(unsigned*)&hi;
        Blo[nn_ * KP + kp] = *(unsigned*)&lo;
    }
    {
        const uint4* A4 = (const uint4*)A;
        for (int i = tid; i < 2048; i += 256) {
            int r = i >> 4, j = i & 15;
            uint4 u = make_uint4(0, 0, 0, 0);
            if (row0 + r < n) u = A4[(size_t)(row0 + r) * 16 + j];
            *(uint4*)(Ahi + r * KP + 4 * j) = u;
        }
    }
    if (tid < 128) {
        sB[tid] = bias[tid];
        sfc[tid] = 0.f;
        if (mode == 1) sWf[tid] = Wfc[tid];
    }
    __syncthreads();

    const int wid = tid >> 5, lane = tid & 31;
    const int grp = lane >> 2, tig = lane & 3;
    const int mrow0 = (wid >> 1) * 32;
    const int ncol0 = (wid & 1) * 64;

    float acc[2][8][4];
#pragma unroll
    for (int mi = 0; mi < 2; mi++)
#pragma unroll
        for (int ni = 0; ni < 8; ni++)
#pragma unroll
            for (int q = 0; q < 4; q++) acc[mi][ni][q] = 0.f;

#pragma unroll
    for (int ks = 0; ks < 8; ks++) {
        const int kw = ks * 8 + tig;
        unsigned ah[2][4];
#pragma unroll
        for (int mi = 0; mi < 2; mi++) {
            int r0 = mrow0 + mi * 16 + grp;
            ah[mi][0] = Ahi[r0 * KP + kw];
            ah[mi][1] = Ahi[(r0 + 8) * KP + kw];
            ah[mi][2] = Ahi[r0 * KP + kw + 4];
            ah[mi][3] = Ahi[(r0 + 8) * KP + kw + 4];
        }
#pragma unroll
        for (int ni = 0; ni < 8; ni++) {
            int nr = ncol0 + ni * 8 + grp;
            unsigned bh0 = Bhi[nr * KP + kw], bh1 = Bhi[nr * KP + kw + 4];
            unsigned bl0 = Blo[nr * KP + kw], bl1 = Blo[nr * KP + kw + 4];
#pragma unroll
            for (int mi = 0; mi < 2; mi++) {
                mma_f16(acc[mi][ni], ah[mi], bh0, bh1);
                mma_f16(acc[mi][ni], ah[mi], bl0, bl1);
            }
        }
    }

#pragma unroll
    for (int mi = 0; mi < 2; mi++) {
        int rA = row0 + mrow0 + mi * 16 + grp;
        float pA = 0.f, pB = 0.f;
#pragma unroll
        for (int ni = 0; ni < 8; ni++) {
            int ccol = ncol0 + ni * 8 + tig * 2;
            float bb0 = sB[ccol], bb1 = sB[ccol + 1];
            float v0 = tanhf(acc[mi][ni][0] + bb0);
            float v1 = tanhf(acc[mi][ni][1] + bb1);
            float v2 = tanhf(acc[mi][ni][2] + bb0);
            float v3 = tanhf(acc[mi][ni][3] + bb1);
            if (mode == 0) {
                if (rA < n)
                    *(__half2*)(outh + (size_t)rA * DD + ccol) =
                        __floats2half2_rn(v0, v1);
                if (rA + 8 < n)
                    *(__half2*)(outh + (size_t)(rA + 8) * DD + ccol) =
                        __floats2half2_rn(v2, v3);
            } else {
                if (rA < n)
                    *(float2*)(outf + (size_t)rA * DD + ccol) =
                        make_float2(v0, v1);
                if (rA + 8 < n)
                    *(float2*)(outf + (size_t)(rA + 8) * DD + ccol) =
                        make_float2(v2, v3);
                float wf0 = sWf[ccol], wf1 = sWf[ccol + 1];
                pA += v0 * wf0 + v1 * wf1;
                pB += v2 * wf0 + v3 * wf1;
            }
        }
        if (mode == 1) {
            int rl = mrow0 + mi * 16 + grp;
            if (rA < n) atomicAdd(&sfc[rl], pA);
            if (rA + 8 < n) atomicAdd(&sfc[rl + 8], pB);
        }
    }
    if (mode == 1) {
        __syncthreads();
        if (tid < 128) {
            int r = row0 + tid;
            if (r < n)
                fcout[r] = 1.0f / (1.0f + expf(-(sfc[tid] + bfc[0])));
        }
    }
}

// ---------------- launch ----------------
extern "C" void kernel_launch(void* const* d_in, const int* in_sizes, int n_in,
                              void* d_out, int out_size) {
    const float* x   = (const float*)d_in[0];
    const int*   eb  = (const int*)d_in[1];
    const float* W1  = (const float*)d_in[2];
    const float* b1  = (const float*)d_in[3];
    const float* W2  = (const float*)d_in[4];
    const float* b2  = (const float*)d_in[5];
    const float* Wfc = (const float*)d_in[6];
    const float* bfc = (const float*)d_in[7];

    int n = in_sizes[0] / DD;
    int e = in_sizes[1] / 2;

    float* out = (float*)d_out;
    float* emb = out + n;

    __half *px, *pa, *pf;
    cudaGetSymbolAddress((void**)&px, g_x16);
    cudaGetSymbolAddress((void**)&pa, g_ax);
    cudaGetSymbolAddress((void**)&pf, g_f16);

    static cudaStream_t s1 = nullptr, s2 = nullptr;
    static cudaEvent_t evF = nullptr, evP = nullptr, evG1 = nullptr,
                       evL = nullptr, evA[NCH], evB[NCH];
    static int init_done = 0;
    const int gemm_smem = (3 * 128 * KP + 384) * 4;
    if (!init_done) {
        cudaFuncSetAttribute(k_gemm,
                             cudaFuncAttributeMaxDynamicSharedMemorySize,
                             gemm_smem);
        cudaStreamCreateWithFlags(&s1, cudaStreamNonBlocking);
        cudaStreamCreateWithFlags(&s2, cudaStreamNonBlocking);
        cudaEventCreateWithFlags(&evF, cudaEventDisableTiming);
        cudaEventCreateWithFlags(&evP, cudaEventDisableTiming);
        cudaEventCreateWithFlags(&evG1, cudaEventDisableTiming);
        cudaEventCreateWithFlags(&evL, cudaEventDisableTiming);
        for (int c = 0; c < NCH; c++) {
            cudaEventCreateWithFlags(&evA[c], cudaEventDisableTiming);
            cudaEventCreateWithFlags(&evB[c], cudaEventDisableTiming);
        }
        init_done = 1;
    }

    const int T = 256;
    int nb = (n + 1023) / 1024;
    int chunk = (((n + NCH - 1) / NCH) + 127) & ~127;

    // fork preprocessing onto s1
    cudaEventRecord(evF, 0);
    cudaStreamWaitEvent(s1, evF, 0);
    k_hist<<<(e + T - 1) / T, T, 0, s1>>>(eb, e);
    k_scanA<<<nb, 1024, 0, s1>>>(n);
    k_scanC<<<(n + T - 1) / T, T, 0, s1>>>(n, e);
    k_fill<<<(e + T - 1) / T, T, 0, s1>>>(eb, e);
    cudaEventRecord(evP, s1);

    // x -> fp16 (overlaps preprocessing)
    k_cvt<<<(n * 16 + T - 1) / T, T>>>(x, n * 16);

    cudaStreamWaitEvent(0, evP, 0);

    // ---- layer 1: agg(x16) chunks pipelined with gemm1 ----
    for (int c = 0; c < NCH; c++) {
        int c0 = c * chunk, c1 = min(n, c0 + chunk);
        if (c0 >= n) break;
        int nodes = c1 - c0;
        k_agg16<<<(nodes * 32 + T - 1) / T, T>>>(px, pa, c0, c1);
        cudaEventRecord(evA[c], 0);
        cudaStreamWaitEvent(s2, evA[c], 0);
        k_gemm<<<(nodes + 127) / 128, 256, gemm_smem, s2>>>(
            pa, W1, b1, pf, nullptr, nullptr, nullptr, nullptr, c0, n, 0);
    }
    cudaEventRecord(evG1, s2);
    cudaStreamWaitEvent(0, evG1, 0);

    // ---- layer 2: agg(f) chunks pipelined with gemm2 (+emb, +fc head) ----
    for (int c = 0; c < NCH; c++) {
        int c0 = c * chunk, c1 = min(n, c0 + chunk);
        if (c0 >= n) break;
        int nodes = c1 - c0;
        k_agg16<<<(nodes * 32 + T - 1) / T, T>>>(pf, pa, c0, c1);
        cudaEventRecord(evB[c], 0);
        cudaStreamWaitEvent(s2, evB[c], 0);
        k_gemm<<<(nodes + 127) / 128, 256, gemm_smem, s2>>>(
            pa, W2, b2, nullptr, emb, Wfc, bfc, out, c0, n, 1);
    }
    cudaEventRecord(evL, s2);
    cudaStreamWaitEvent(0, evL, 0);
}

// round 14
// speedup vs baseline: 1.1329x; 1.0085x over previous
#include <cuda_runtime.h>
#include <cuda_fp16.h>
#include <math.h>
#include <stdint.h>

#define NN 100000
#define EE 1600000
#define DD 128
#define KP 68          // padded smem row stride in 32-bit words
#define NCH 4          // pipeline chunks
#define FULLM 0xFFFFFFFFu

// ---------------- device scratch (no allocations allowed) ----------------
__device__ int    g_rowptr[NN + 1];
__device__ int    g_cnt[NN];          // zero-init; re-zeroed by k_scanC
__device__ int    g_cursor[NN];
__device__ float  g_dinv[NN];
__device__ int2   g_cedge[EE];        // (src, dinv[src] bits), grouped by dst
__device__ int    g_bsums[128];
__device__ __half g_x16[(size_t)NN * DD];  // fp16 copy of input x
__device__ __half g_ax[(size_t)NN * DD];   // aggregated rows (both layers)
__device__ __half g_f16[(size_t)NN * DD];  // layer-1 activations f

// ---------------- x -> fp16 ----------------
__global__ void k_cvt(const float* __restrict__ x, int total8) {
    int i = blockIdx.x * blockDim.x + threadIdx.x;
    if (i >= total8) return;
    const float4* x4 = (const float4*)x;
    float4 a = x4[i * 2], b = x4[i * 2 + 1];
    __half2 h0 = __floats2half2_rn(a.x, a.y);
    __half2 h1 = __floats2half2_rn(a.z, a.w);
    __half2 h2 = __floats2half2_rn(b.x, b.y);
    __half2 h3 = __floats2half2_rn(b.z, b.w);
    uint4 u;
    u.x = *(unsigned*)&h0; u.y = *(unsigned*)&h1;
    u.z = *(unsigned*)&h2; u.w = *(unsigned*)&h3;
    ((uint4*)g_x16)[i] = u;
}

// ---------------- edge dtype detection (per warp) ----------------
__device__ __forceinline__ int detect64(const int* __restrict__ eb) {
    unsigned nz = 0;
#pragma unroll
    for (int i = (threadIdx.x & 31); i < 128; i += 32)
        nz |= (eb[2 * i + 1] != 0);
    return __ballot_sync(FULLM, nz) == 0;
}

// ---------------- preprocessing ----------------
__global__ void k_hist(const int* __restrict__ eb, int e) {
    int is64 = detect64(eb);
    int i = blockIdx.x * blockDim.x + threadIdx.x;
    if (i >= e) return;
    int d = is64 ? eb[2 * (e + i)] : eb[e + i];
    atomicAdd(&g_cnt[d], 1);
}

__global__ void k_scanA(int n) {
    __shared__ int sh[1024];
    int gi = blockIdx.x * 1024 + threadIdx.x;
    int v = (gi < n) ? g_cnt[gi] : 0;
    sh[threadIdx.x] = v;
    __syncthreads();
    for (int off = 1; off < 1024; off <<= 1) {
        int x = sh[threadIdx.x];
        int y = (threadIdx.x >= off) ? sh[threadIdx.x - off] : 0;
        __syncthreads();
        sh[threadIdx.x] = x + y;
        __syncthreads();
    }
    int incl = sh[threadIdx.x];
    if (gi < n) g_rowptr[gi] = incl - v;
    if (threadIdx.x == 1023) g_bsums[blockIdx.x] = incl;
}

__global__ void k_scanC(int n, int e) {
    __shared__ int sh[128];
    int t = threadIdx.x;
    int nb = (n + 1023) >> 10;
    if (t < 128) sh[t] = (t < nb) ? g_bsums[t] : 0;
    __syncthreads();
    for (int off = 1; off < 128; off <<= 1) {
        int x = 0, y = 0;
        if (t < 128) { x = sh[t]; y = (t >= off) ? sh[t - off] : 0; }
        __syncthreads();
        if (t < 128) sh[t] = x + y;
        __syncthreads();
    }
    int i = blockIdx.x * blockDim.x + t;
    if (i < n) {
        int blk = i >> 10;
        int ex = blk ? sh[blk - 1] : 0;
        int rp = g_rowptr[i] + ex;
        g_rowptr[i] = rp;
        g_cursor[i] = rp;
        g_dinv[i] = rsqrtf((float)(g_cnt[i] + 1));
        g_cnt[i] = 0;
    }
    if (blockIdx.x == 0 && t == 0) g_rowptr[n] = e;
}

// fill restricted to dst range [d0, d1) — lets CSR for low nodes finish early.
__global__ void k_fill(const int* __restrict__ eb, int e, int d0, int d1) {
    int is64 = detect64(eb);
    int i = blockIdx.x * blockDim.x + threadIdx.x;
    if (i >= e) return;
    int d = is64 ? eb[2 * (e + i)] : eb[e + i];
    if (d < d0 || d >= d1) return;
    int s = is64 ? eb[2 * i] : eb[i];
    int p = atomicAdd(&g_cursor[d], 1);
    g_cedge[p] = make_int2(s, __float_as_int(g_dinv[s]));
}

// ---------------- aggregation: O[d] = dinv[d]*(sum_s dinv[s]*X[s] + dinv[d]*X[d])
__device__ __forceinline__ void acc8(float* a, uint4 u, float w) {
    float2 f;
    f = __half22float2(*(__half2*)&u.x); a[0] += w * f.x; a[1] += w * f.y;
    f = __half22float2(*(__half2*)&u.y); a[2] += w * f.x; a[3] += w * f.y;
    f = __half22float2(*(__half2*)&u.z); a[4] += w * f.x; a[5] += w * f.y;
    f = __half22float2(*(__half2*)&u.w); a[6] += w * f.x; a[7] += w * f.y;
}

__global__ void __launch_bounds__(256) k_agg16(
    const __half* __restrict__ H,
    __half* __restrict__ outh, int n0, int n1) {
    int node = n0 + ((blockIdx.x * blockDim.x + threadIdx.x) >> 5);
    int lane = threadIdx.x & 31;
    if (node >= n1) return;
    int p = lane >> 4, c = lane & 15;
    const uint4* H4 = (const uint4*)H;
    float di = g_dinv[node];

    float acc[8];
    {
        uint4 u = H4[(size_t)node * 16 + c];
        float w = (p == 0) ? di : 0.f;
        float2 f;
        f = __half22float2(*(__half2*)&u.x); acc[0] = w * f.x; acc[1] = w * f.y;
        f = __half22float2(*(__half2*)&u.y); acc[2] = w * f.x; acc[3] = w * f.y;
        f = __half22float2(*(__half2*)&u.z); acc[4] = w * f.x; acc[5] = w * f.y;
        f = __half22float2(*(__half2*)&u.w); acc[6] = w * f.x; acc[7] = w * f.y;
    }

    int beg = g_rowptr[node];
    int cnt = g_rowptr[node + 1] - beg;
    int done = 0;
    while (done < cnt) {
        int m = cnt - done;
        if (m > 32) m = 32;
        int idx = 0;
        float wv = 0.f;
        if (lane < m) {
            int2 ew = g_cedge[beg + done + lane];
            idx = ew.x;
            wv = __int_as_float(ew.y);
        }
        int j = 0;
        for (; j + 8 <= m; j += 8) {
            int i0 = __shfl_sync(FULLM, idx, j + p);
            float w0 = __shfl_sync(FULLM, wv, j + p);
            int i1 = __shfl_sync(FULLM, idx, j + 2 + p);
            float w1 = __shfl_sync(FULLM, wv, j + 2 + p);
            int i2 = __shfl_sync(FULLM, idx, j + 4 + p);
            float w2 = __shfl_sync(FULLM, wv, j + 4 + p);
            int i3 = __shfl_sync(FULLM, idx, j + 6 + p);
            float w3 = __shfl_sync(FULLM, wv, j + 6 + p);
            uint4 u0 = H4[(size_t)i0 * 16 + c];
            uint4 u1 = H4[(size_t)i1 * 16 + c];
            uint4 u2 = H4[(size_t)i2 * 16 + c];
            uint4 u3 = H4[(size_t)i3 * 16 + c];
            acc8(acc, u0, w0);
            acc8(acc, u1, w1);
            acc8(acc, u2, w2);
            acc8(acc, u3, w3);
        }
        for (; j + 2 <= m; j += 2) {
            int i0 = __shfl_sync(FULLM, idx, j + p);
            float w0 = __shfl_sync(FULLM, wv, j + p);
            uint4 u0 = H4[(size_t)i0 * 16 + c];
            acc8(acc, u0, w0);
        }
        if (j < m) {
            int i0 = __shfl_sync(FULLM, idx, j);
            float w0 = __shfl_sync(FULLM, wv, j);
            if (p == 0) {
                uint4 u0 = H4[(size_t)i0 * 16 + c];
                acc8(acc, u0, w0);
            }
        }
        done += m;
    }

#pragma unroll
    for (int k = 0; k < 8; k++)
        acc[k] += __shfl_xor_sync(FULLM, acc[k], 16);

    if (p == 0) {
        __half2 h0 = __floats2half2_rn(di * acc[0], di * acc[1]);
        __half2 h1 = __floats2half2_rn(di * acc[2], di * acc[3]);
        __half2 h2 = __floats2half2_rn(di * acc[4], di * acc[5]);
        __half2 h3 = __floats2half2_rn(di * acc[6], di * acc[7]);
        uint4 u;
        u.x = *(unsigned*)&h0; u.y = *(unsigned*)&h1;
        u.z = *(unsigned*)&h2; u.w = *(unsigned*)&h3;
        ((uint4*)outh)[(size_t)node * 16 + c] = u;
    }
}

// ---------------- GEMM + fused activation epilogue ----------------
__device__ __forceinline__ void mma_f16(float* d, const unsigned* a,
                                        unsigned b0, unsigned b1) {
    asm volatile(
        "mma.sync.aligned.m16n8k16.row.col.f32.f16.f16.f32 "
        "{%0,%1,%2,%3}, {%4,%5,%6,%7}, {%8,%9}, {%0,%1,%2,%3};\n"
        : "+f"(d[0]), "+f"(d[1]), "+f"(d[2]), "+f"(d[3])
        : "r"(a[0]), "r"(a[1]), "r"(a[2]), "r"(a[3]), "r"(b0), "r"(b1));
}

__global__ void __launch_bounds__(256) k_gemm(
    const __half* __restrict__ A, const float* __restrict__ W,
    const float* __restrict__ bias,
    __half* __restrict__ outh,                    // mode 0
    float* __restrict__ outf,                     // mode 1: emb
    const float* __restrict__ Wfc, const float* __restrict__ bfc,
    float* __restrict__ fcout,                    // mode 1: fc head
    int n0, int n, int mode) {
    extern __shared__ unsigned smu[];
    unsigned* Ahi = smu;
    unsigned* Bhi = Ahi + 128 * KP;
    unsigned* Blo = Bhi + 128 * KP;
    float* sfc = (float*)(Blo + 128 * KP);
    float* sWf = sfc + 128;
    float* sB  = sWf + 128;
    const int tid = threadIdx.x;
    const int row0 = n0 + blockIdx.x * 128;

    for (int i = tid; i < 8192; i += 256) {
        int nn_ = i & 127;
        int kp = i >> 7;
        int k = kp * 2;
        float w0 = W[k * DD + nn_];
        float w1 = W[(k + 1) * DD + nn_];
        __half h0 = __float2half_rn(w0), h1 = __float2half_rn(w1);
        __half2 hi = __halves2half2(h0, h1);
        __half2 lo = __floats2half2_rn(w0 - __half2float(h0),
                                       w1 - __half2float(h1));
        Bhi[nn_ * KP + kp] = *(unsigned*)&hi;
        Blo[nn_ * KP + kp] = *(unsigned*)&lo;
    }
    {
        const uint4* A4 = (const uint4*)A;
        for (int i = tid; i < 2048; i += 256) {
            int r = i >> 4, j = i & 15;
            uint4 u = make_uint4(0, 0, 0, 0);
            if (row0 + r < n) u = A4[(size_t)(row0 + r) * 16 + j];
            *(uint4*)(Ahi + r * KP + 4 * j) = u;
        }
    }
    if (tid < 128) {
        sB[tid] = bias[tid];
        sfc[tid] = 0.f;
        if (mode == 1) sWf[tid] = Wfc[tid];
    }
    __syncthreads();

    const int wid = tid >> 5, lane = tid & 31;
    const int grp = lane >> 2, tig = lane & 3;
    const int mrow0 = (wid >> 1) * 32;
    const int ncol0 = (wid & 1) * 64;

    float acc[2][8][4];
#pragma unroll
    for (int mi = 0; mi < 2; mi++)
#pragma unroll
        for (int ni = 0; ni < 8; ni++)
#pragma unroll
            for (int q = 0; q < 4; q++) acc[mi][ni][q] = 0.f;

#pragma unroll
    for (int ks = 0; ks < 8; ks++) {
        const int kw = ks * 8 + tig;
        unsigned ah[2][4];
#pragma unroll
        for (int mi = 0; mi < 2; mi++) {
            int r0 = mrow0 + mi * 16 + grp;
            ah[mi][0] = Ahi[r0 * KP + kw];
            ah[mi][1] = Ahi[(r0 + 8) * KP + kw];
            ah[mi][2] = Ahi[r0 * KP + kw + 4];
            ah[mi][3] = Ahi[(r0 + 8) * KP + kw + 4];
        }
#pragma unroll
        for (int ni = 0; ni < 8; ni++) {
            int nr = ncol0 + ni * 8 + grp;
            unsigned bh0 = Bhi[nr * KP + kw], bh1 = Bhi[nr * KP + kw + 4];
            unsigned bl0 = Blo[nr * KP + kw], bl1 = Blo[nr * KP + kw + 4];
#pragma unroll
            for (int mi = 0; mi < 2; mi++) {
                mma_f16(acc[mi][ni], ah[mi], bh0, bh1);
                mma_f16(acc[mi][ni], ah[mi], bl0, bl1);
            }
        }
    }

#pragma unroll
    for (int mi = 0; mi < 2; mi++) {
        int rA = row0 + mrow0 + mi * 16 + grp;
        float pA = 0.f, pB = 0.f;
#pragma unroll
        for (int ni = 0; ni < 8; ni++) {
            int ccol = ncol0 + ni * 8 + tig * 2;
            float bb0 = sB[ccol], bb1 = sB[ccol + 1];
            float v0 = tanhf(acc[mi][ni][0] + bb0);
            float v1 = tanhf(acc[mi][ni][1] + bb1);
            float v2 = tanhf(acc[mi][ni][2] + bb0);
            float v3 = tanhf(acc[mi][ni][3] + bb1);
            if (mode == 0) {
                if (rA < n)
                    *(__half2*)(outh + (size_t)rA * DD + ccol) =
                        __floats2half2_rn(v0, v1);
                if (rA + 8 < n)
                    *(__half2*)(outh + (size_t)(rA + 8) * DD + ccol) =
                        __floats2half2_rn(v2, v3);
            } else {
                if (rA < n)
                    *(float2*)(outf + (size_t)rA * DD + ccol) =
                        make_float2(v0, v1);
                if (rA + 8 < n)
                    *(float2*)(outf + (size_t)(rA + 8) * DD + ccol) =
                        make_float2(v2, v3);
                float wf0 = sWf[ccol], wf1 = sWf[ccol + 1];
                pA += v0 * wf0 + v1 * wf1;
                pB += v2 * wf0 + v3 * wf1;
            }
        }
        if (mode == 1) {
            int rl = mrow0 + mi * 16 + grp;
            if (rA < n) atomicAdd(&sfc[rl], pA);
            if (rA + 8 < n) atomicAdd(&sfc[rl + 8], pB);
        }
    }
    if (mode == 1) {
        __syncthreads();
        if (tid < 128) {
            int r = row0 + tid;
            if (r < n)
                fcout[r] = 1.0f / (1.0f + expf(-(sfc[tid] + bfc[0])));
        }
    }
}

// ---------------- launch ----------------
static inline int al128(int v) { return (v + 127) & ~127; }

extern "C" void kernel_launch(void* const* d_in, const int* in_sizes, int n_in,
                              void* d_out, int out_size) {
    const float* x   = (const float*)d_in[0];
    const int*   eb  = (const int*)d_in[1];
    const float* W1  = (const float*)d_in[2];
    const float* b1  = (const float*)d_in[3];
    const float* W2  = (const float*)d_in[4];
    const float* b2  = (const float*)d_in[5];
    const float* Wfc = (const float*)d_in[6];
    const float* bfc = (const float*)d_in[7];

    int n = in_sizes[0] / DD;
    int e = in_sizes[1] / 2;

    float* out = (float*)d_out;
    float* emb = out + n;

    __half *px, *pa, *pf;
    cudaGetSymbolAddress((void**)&px, g_x16);
    cudaGetSymbolAddress((void**)&pa, g_ax);
    cudaGetSymbolAddress((void**)&pf, g_f16);

    static cudaStream_t s1 = nullptr, s2 = nullptr;
    static cudaEvent_t evF = nullptr, evP0 = nullptr, evP = nullptr,
                       evG1 = nullptr, evL = nullptr, evA[NCH], evB[NCH];
    static int init_done = 0;
    const int gemm_smem = (3 * 128 * KP + 384) * 4;
    if (!init_done) {
        cudaFuncSetAttribute(k_gemm,
                             cudaFuncAttributeMaxDynamicSharedMemorySize,
                             gemm_smem);
        cudaStreamCreateWithFlags(&s1, cudaStreamNonBlocking);
        cudaStreamCreateWithFlags(&s2, cudaStreamNonBlocking);
        cudaEventCreateWithFlags(&evF, cudaEventDisableTiming);
        cudaEventCreateWithFlags(&evP0, cudaEventDisableTiming);
        cudaEventCreateWithFlags(&evP, cudaEventDisableTiming);
        cudaEventCreateWithFlags(&evG1, cudaEventDisableTiming);
        cudaEventCreateWithFlags(&evL, cudaEventDisableTiming);
        for (int c = 0; c < NCH; c++) {
            cudaEventCreateWithFlags(&evA[c], cudaEventDisableTiming);
            cudaEventCreateWithFlags(&evB[c], cudaEventDisableTiming);
        }
        init_done = 1;
    }

    const int T = 256;
    int nb = (n + 1023) / 1024;

    // ---- descending chunk schedules ----
    // layer 1: chunk0 = first half (matches fill pass 0), rest descending
    int nhalf = al128(n / 2);
    int r = n - nhalf;
    int b1a = nhalf + al128(r / 2);
    int b1b = b1a + al128(r / 4);
    int L1b[NCH + 1] = {0, nhalf, b1a, b1b, n};
    // layer 2: 40% / 30% / rest split descending
    int d1_ = al128((int)((long long)n * 2 / 5));
    int d2_ = d1_ + al128((int)((long long)n * 3 / 10));
    int d3_ = d2_ + al128((n - d2_) * 3 / 5);
    int L2b[NCH + 1] = {0, d1_, d2_, d3_, n};

    // fork preprocessing onto s1 (fill split into two dst-range passes)
    cudaEventRecord(evF, 0);
    cudaStreamWaitEvent(s1, evF, 0);
    k_hist<<<(e + T - 1) / T, T, 0, s1>>>(eb, e);
    k_scanA<<<nb, 1024, 0, s1>>>(n);
    k_scanC<<<(n + T - 1) / T, T, 0, s1>>>(n, e);
    k_fill<<<(e + T - 1) / T, T, 0, s1>>>(eb, e, 0, nhalf);
    cudaEventRecord(evP0, s1);
    k_fill<<<(e + T - 1) / T, T, 0, s1>>>(eb, e, nhalf, n);
    cudaEventRecord(evP, s1);

    // x -> fp16 (overlaps preprocessing)
    k_cvt<<<(n * 16 + T - 1) / T, T>>>(x, n * 16);

    // ---- layer 1: agg(x16) chunks pipelined with gemm1 ----
    for (int c = 0; c < NCH; c++) {
        int c0 = L1b[c], c1 = L1b[c + 1];
        if (c0 >= c1) continue;
        int nodes = c1 - c0;
        if (c == 0) cudaStreamWaitEvent(0, evP0, 0);  // chunk0 needs fill-lo only
        if (c == 1) cudaStreamWaitEvent(0, evP, 0);   // rest need fill-hi
        k_agg16<<<(nodes * 32 + T - 1) / T, T>>>(px, pa, c0, c1);
        cudaEventRecord(evA[c], 0);
        cudaStreamWaitEvent(s2, evA[c], 0);
        k_gemm<<<(nodes + 127) / 128, 256, gemm_smem, s2>>>(
            pa, W1, b1, pf, nullptr, nullptr, nullptr, nullptr, c0, n, 0);
    }
    cudaEventRecord(evG1, s2);
    cudaStreamWaitEvent(0, evG1, 0);

    // ---- layer 2: agg(f) chunks pipelined with gemm2 (+emb, +fc head) ----
    for (int c = 0; c < NCH; c++) {
        int c0 = L2b[c], c1 = L2b[c + 1];
        if (c0 >= c1) continue;
        int nodes = c1 - c0;
        k_agg16<<<(nodes * 32 + T - 1) / T, T>>>(pf, pa, c0, c1);
        cudaEventRecord(evB[c], 0);
        cudaStreamWaitEvent(s2, evB[c], 0);
        k_gemm<<<(nodes + 127) / 128, 256, gemm_smem, s2>>>(
            pa, W2, b2, nullptr, emb, Wfc, bfc, out, c0, n, 1);
    }
    cudaEventRecord(evL, s2);
    cudaStreamWaitEvent(0, evL, 0);
}